// round 9
// baseline (speedup 1.0000x reference)
#include <cuda_runtime.h>

// out[b,c] = exp( sum_s x[b, chunk_map[c,s]] * wSupp[c,s] )
// B=4096, NCLASS=1000, NSUPP=64, NCHUNK=4096

#define NCLASS 1000
#define NSUPP  64
#define NCHUNK 4096
#define BATCH  4096
#define NB     4       // batch rows per CTA (64 KB tile -> 3 CTAs/SM)
#define THREADS 512
#define OCTETS (NCLASS / 8)   // 125 phase octets (8 consecutive classes)

// SoA packed schedule, transposed [chunk][class] for coalesced LDG:
//   g_idx: 8 u16 indices per int4   -> 8 chunks of 8 slots
//   g_w  : 4 f32 weights per float4 -> 16 chunks of 4 slots
// Schedule: slot p of class c prefers an entry with bank group
// (idx&7) == (p + c) & 7 -> the 8 lanes of an LDS.128 phase (8 consecutive
// classes) read 8 distinct bank groups. Overflow entries are spill-placed
// with CROSS-CLASS coordination so deviating lanes still avoid collisions.
__device__ int4   g_idx[(NSUPP / 8) * NCLASS];
__device__ float4 g_w[(NSUPP / 4) * NCLASS];

__device__ __forceinline__ void sched_store(int c, int slot, int idx, float wv) {
    ((unsigned short*)g_idx)[((slot >> 3) * NCLASS + c) * 8 + (slot & 7)] =
        (unsigned short)idx;
    ((float*)g_w)[((slot >> 2) * NCLASS + c) * 4 + (slot & 3)] = wv;
}

// One WARP per phase octet. Lanes 0-7 = the octet's 8 classes.
// T[k] = taken-groups table: field r (8 bits) of T[k] is the set of bank
// groups read at step p = r + 8k by already-placed entries of the octet.
__global__ void pack_kernel(const float* __restrict__ w,
                            const int* __restrict__ cmap) {
    const int lane  = threadIdx.x & 31;
    const int octet = blockIdx.x * (blockDim.x >> 5) + (threadIdx.x >> 5);
    if (octet >= OCTETS) return;
    const int  c      = octet * 8 + (lane & 7);
    const bool active = (lane < 8);

    const unsigned long long PRE = 0x0101010101010101ull;
    const int*   row  = cmap + c * NSUPP;
    const float* wrow = w + c * NSUPP;

    unsigned long long cnt = 0ull, fm = 0ull;
    unsigned long long T0 = 0, T1 = 0, T2 = 0, T3 = 0,
                       T4 = 0, T5 = 0, T6 = 0, T7 = 0;

    if (active) {
        // counts (8x8-bit packed)
#pragma unroll 8
        for (int e = 0; e < NSUPP; ++e)
            cnt += 1ull << ((row[e] & 7) * 8);

        // free-slot mask + taken-table contributions
#pragma unroll
        for (int r = 0; r < 8; ++r) {
            int hg = (r + c) & 7;
            int ch = (int)((cnt >> (hg * 8)) & 0xff);
            if (ch > 8) ch = 8;
            unsigned long long low =
                (ch >= 8) ? ~0ull : ((1ull << (8 * ch)) - 1ull);
            fm |= (PRE << r) & ~low;                  // holes at residue r
            unsigned long long gb =
                ((unsigned long long)(1u << hg)) << (r * 8);
#pragma unroll
            for (int k = 0; k < 8; ++k) {
                unsigned long long add = (k < ch) ? gb : 0ull;
                if (k == 0) T0 |= add; else if (k == 1) T1 |= add;
                else if (k == 2) T2 |= add; else if (k == 3) T3 |= add;
                else if (k == 4) T4 |= add; else if (k == 5) T5 |= add;
                else if (k == 6) T6 |= add; else T7 |= add;
            }
        }
        // preferred placements (stores to schedule)
        unsigned long long cur = 0ull;
#pragma unroll 4
        for (int e = 0; e < NSUPP; ++e) {
            int idx = row[e], gg = idx & 7;
            int j = (int)((cur >> (gg * 8)) & 0xff);
            cur += 1ull << (gg * 8);
            if (j < 8)
                sched_store(c, ((gg - c) & 7) + 8 * j, idx, wrow[e]);
        }
    }
    // warp OR-reduce T over the 8 lanes -> octet-global taken state
#pragma unroll
    for (int off = 4; off; off >>= 1) {
        T0 |= __shfl_xor_sync(0xffffffffu, T0, off);
        T1 |= __shfl_xor_sync(0xffffffffu, T1, off);
        T2 |= __shfl_xor_sync(0xffffffffu, T2, off);
        T3 |= __shfl_xor_sync(0xffffffffu, T3, off);
        T4 |= __shfl_xor_sync(0xffffffffu, T4, off);
        T5 |= __shfl_xor_sync(0xffffffffu, T5, off);
        T6 |= __shfl_xor_sync(0xffffffffu, T6, off);
        T7 |= __shfl_xor_sync(0xffffffffu, T7, off);
    }

    // spill placement, round-robin over the 8 classes
    for (int turn = 0; turn < 8; ++turn) {
        if (active && (lane & 7) == turn) {
            unsigned long long cur = 0ull;
            for (int e = 0; e < NSUPP; ++e) {
                int idx = row[e], gg = idx & 7;
                int j = (int)((cur >> (gg * 8)) & 0xff);
                cur += 1ull << (gg * 8);
                if (j < 8) continue;
                // branch-free candidate: own free slot whose step lacks gg
                int slot = -1;
#pragma unroll
                for (int k = 0; k < 8; ++k) {
                    unsigned long long tk =
                        (k == 0) ? T0 : (k == 1) ? T1 : (k == 2) ? T2 :
                        (k == 3) ? T3 : (k == 4) ? T4 : (k == 5) ? T5 :
                        (k == 6) ? T6 : T7;
                    unsigned long long bits = (tk >> gg) & PRE;
                    unsigned taken8 =
                        (unsigned)((bits * 0x0102040810204080ull) >> 56);
                    unsigned candk =
                        ((unsigned)(fm >> (8 * k)) & 0xffu) & ~taken8 & 0xffu;
                    if (slot < 0 && candk) slot = 8 * k + (__ffs(candk) - 1);
                }
                if (slot < 0) slot = __ffsll((long long)fm) - 1;  // collide
                fm &= ~(1ull << slot);
                int kk = slot >> 3, rr = slot & 7;
                unsigned long long gb =
                    ((unsigned long long)(1u << gg)) << (rr * 8);
                if (kk == 0) T0 |= gb; else if (kk == 1) T1 |= gb;
                else if (kk == 2) T2 |= gb; else if (kk == 3) T3 |= gb;
                else if (kk == 4) T4 |= gb; else if (kk == 5) T5 |= gb;
                else if (kk == 6) T6 |= gb; else T7 |= gb;
                sched_store(c, slot, idx, wrow[e]);
            }
        }
        // broadcast updated taken state from this turn's lane
        T0 = __shfl_sync(0xffffffffu, T0, turn);
        T1 = __shfl_sync(0xffffffffu, T1, turn);
        T2 = __shfl_sync(0xffffffffu, T2, turn);
        T3 = __shfl_sync(0xffffffffu, T3, turn);
        T4 = __shfl_sync(0xffffffffu, T4, turn);
        T5 = __shfl_sync(0xffffffffu, T5, turn);
        T6 = __shfl_sync(0xffffffffu, T6, turn);
        T7 = __shfl_sync(0xffffffffu, T7, turn);
    }
}

__global__ void __launch_bounds__(THREADS, 3)
supp_kernel(const float* __restrict__ x, float* __restrict__ out) {
    // xs[idx] = x[b0..b0+3][idx]; gather bank group = idx&7.
    extern __shared__ float4 smem[];
    float4* xs = smem;

    const int b0 = blockIdx.x * NB;

    // --- Stage x tile: 4 rows x 4096 floats = 64 KB ---
    for (int i = threadIdx.x; i < NCHUNK; i += THREADS) {
        const float* xb = x + (size_t)b0 * NCHUNK + i;
        float t0 = xb[0 * NCHUNK];
        float t1 = xb[1 * NCHUNK];
        float t2 = xb[2 * NCHUNK];
        float t3 = xb[3 * NCHUNK];
        xs[i] = make_float4(t0, t1, t2, t3);
    }
    __syncthreads();

    // --- Gather + dot: thread = class (2 per thread), 4 batch rows each ---
    for (int c = threadIdx.x; c < NCLASS; c += THREADS) {
        float a0 = 0.f, a1 = 0.f, a2 = 0.f, a3 = 0.f;
#pragma unroll 2
        for (int k = 0; k < NSUPP / 8; ++k) {       // 8 entries per chunk
            int4   pi = g_idx[k * NCLASS + c];      // 8 u16 idx, LDG.128
            float4 wa = g_w[(2 * k) * NCLASS + c];  // slots 8k..8k+3
            float4 wb = g_w[(2 * k + 1) * NCLASS + c];

            int i0 = pi.x & 0xffff, i1 = ((unsigned)pi.x) >> 16;
            int i2 = pi.y & 0xffff, i3 = ((unsigned)pi.y) >> 16;
            int i4 = pi.z & 0xffff, i5 = ((unsigned)pi.z) >> 16;
            int i6 = pi.w & 0xffff, i7 = ((unsigned)pi.w) >> 16;

            float4 v;
            v = xs[i0]; a0 = fmaf(v.x, wa.x, a0); a1 = fmaf(v.y, wa.x, a1);
                        a2 = fmaf(v.z, wa.x, a2); a3 = fmaf(v.w, wa.x, a3);
            v = xs[i1]; a0 = fmaf(v.x, wa.y, a0); a1 = fmaf(v.y, wa.y, a1);
                        a2 = fmaf(v.z, wa.y, a2); a3 = fmaf(v.w, wa.y, a3);
            v = xs[i2]; a0 = fmaf(v.x, wa.z, a0); a1 = fmaf(v.y, wa.z, a1);
                        a2 = fmaf(v.z, wa.z, a2); a3 = fmaf(v.w, wa.z, a3);
            v = xs[i3]; a0 = fmaf(v.x, wa.w, a0); a1 = fmaf(v.y, wa.w, a1);
                        a2 = fmaf(v.z, wa.w, a2); a3 = fmaf(v.w, wa.w, a3);
            v = xs[i4]; a0 = fmaf(v.x, wb.x, a0); a1 = fmaf(v.y, wb.x, a1);
                        a2 = fmaf(v.z, wb.x, a2); a3 = fmaf(v.w, wb.x, a3);
            v = xs[i5]; a0 = fmaf(v.x, wb.y, a0); a1 = fmaf(v.y, wb.y, a1);
                        a2 = fmaf(v.z, wb.y, a2); a3 = fmaf(v.w, wb.y, a3);
            v = xs[i6]; a0 = fmaf(v.x, wb.z, a0); a1 = fmaf(v.y, wb.z, a1);
                        a2 = fmaf(v.z, wb.z, a2); a3 = fmaf(v.w, wb.z, a3);
            v = xs[i7]; a0 = fmaf(v.x, wb.w, a0); a1 = fmaf(v.y, wb.w, a1);
                        a2 = fmaf(v.z, wb.w, a2); a3 = fmaf(v.w, wb.w, a3);
        }

        float* o = out + (size_t)b0 * NCLASS + c;
        o[0 * NCLASS] = __expf(a0);
        o[1 * NCLASS] = __expf(a1);
        o[2 * NCLASS] = __expf(a2);
        o[3 * NCLASS] = __expf(a3);
    }
}

extern "C" void kernel_launch(void* const* d_in, const int* in_sizes, int n_in,
                              void* d_out, int out_size) {
    const float* x    = (const float*)d_in[0];  // [4096, 4096] f32
    const float* w    = (const float*)d_in[1];  // [1000, 64]   f32
    const int*   cmap = (const int*)d_in[2];    // [1000, 64]   i32
    float*       out  = (float*)d_out;          // [4096, 1000] f32

    (void)in_sizes; (void)n_in; (void)out_size;

    static const size_t smem_bytes = NCHUNK * sizeof(float4);  // 64 KB
    cudaFuncSetAttribute(supp_kernel,
                         cudaFuncAttributeMaxDynamicSharedMemorySize,
                         (int)smem_bytes);

    // 4 warps (octets) per CTA, 125 octets total
    pack_kernel<<<(OCTETS + 3) / 4, 128>>>(w, cmap);
    supp_kernel<<<BATCH / NB, THREADS, smem_bytes>>>(x, out);
}

// round 10
// speedup vs baseline: 1.6440x; 1.6440x over previous
#include <cuda_runtime.h>

// out[b,c] = exp( sum_s x[b, chunk_map[c,s]] * wSupp[c,s] )
// B=4096, NCLASS=1000, NSUPP=64, NCHUNK=4096

#define NCLASS 1000
#define NSUPP  64
#define NCHUNK 4096
#define BATCH  4096
#define NB     4       // batch rows per CTA (64 KB tile -> 3 CTAs/SM)
#define THREADS 512

// SoA packed schedule, transposed [chunk][class] for coalesced LDG:
//   g_idx: 8 u16 indices per int4   -> 8 chunks of 8 slots
//   g_w  : 4 f32 weights per float4 -> 16 chunks of 4 slots
// Schedule: slot p of class c prefers an entry with bank group
// (idx&7) == (p + c) & 7, so the 8 lanes of each LDS.128 phase
// (8 consecutive classes) hit 8 distinct bank groups. Overflow entries
// (group count > 8) spill into leftover slots; the spill pop order is
// rotated per class so octet spills decorrelate across steps.
__device__ int4   g_idx[(NSUPP / 8) * NCLASS];
__device__ float4 g_w[(NSUPP / 4) * NCLASS];

// One thread per (class, bank-group). Branch-free: group counts and running
// ranks live in packed 8x8-bit u64 counters; spill slots come from a
// free-slot bitmask popped with ffsll (O(1) per spill, no inner scans).
__global__ void pack_kernel(const float* __restrict__ w,
                            const int* __restrict__ cmap) {
    int t = blockIdx.x * blockDim.x + threadIdx.x;
    if (t >= NCLASS * 8) return;
    int c = t >> 3;
    int g = t & 7;

    const int*   row  = cmap + c * NSUPP;
    const float* wrow = w + c * NSUPP;
    const unsigned long long PRE = 0x0101010101010101ull;

    // pass 1: per-group counts (8 counters x 8 bits in one u64)
    unsigned long long cnt = 0ull;
#pragma unroll 8
    for (int e = 0; e < NSUPP; ++e)
        cnt += 1ull << ((row[e] & 7) * 8);

    // free-slot bitmask: slot p (= residue r, depth k) is free iff
    // k >= min(cnt[hostgroup], 8), hostgroup(r) = (r + c) & 7.
    unsigned long long freemask = 0ull;
#pragma unroll
    for (int r = 0; r < 8; ++r) {
        int hg = (r + c) & 7;
        int ch = (int)((cnt >> (hg * 8)) & 0xff);
        if (ch > 8) ch = 8;
        unsigned long long lowbits =
            (ch >= 8) ? ~0ull : ((1ull << (8 * ch)) - 1ull);
        freemask |= (PRE << r) & ~lowbits;
    }

    unsigned short* idx_out = (unsigned short*)g_idx;
    float*          w_out   = (float*)g_w;

    // pass 2: branch-free placement; spills pop the free mask starting at a
    // class-dependent rotation so the octet's spills spread over steps.
    unsigned long long cur = 0ull;
    unsigned long long fm  = freemask;
    const int rotamt = (c & 7) * 8;
#pragma unroll 4
    for (int e = 0; e < NSUPP; ++e) {
        int idx = row[e];
        int gg  = idx & 7;
        int j   = (int)((cur >> (gg * 8)) & 0xff);
        cur += 1ull << (gg * 8);

        bool isspill = (j >= 8);
        int pref = ((gg - c) & 7) + 8 * j;          // valid when j < 8
        // rotated pop: first free slot at/after slot 'rotamt' (wraps)
        unsigned long long fmr =
            (fm >> rotamt) | (fm << ((64 - rotamt) & 63));
        int sp   = (__ffsll((long long)fmr) - 1 + rotamt) & 63;
        int slot = isspill ? sp : pref;
        fm       = isspill ? (fm & ~(1ull << sp)) : fm;

        if (gg == g) {                               // predicated store
            idx_out[((slot >> 3) * NCLASS + c) * 8 + (slot & 7)] =
                (unsigned short)idx;
            w_out[((slot >> 2) * NCLASS + c) * 4 + (slot & 3)] = wrow[e];
        }
    }
}

__global__ void __launch_bounds__(THREADS, 3)
supp_kernel(const float* __restrict__ x, float* __restrict__ out) {
    // xs[idx] = x[b0..b0+3][idx]; gather bank group = idx&7.
    extern __shared__ float4 smem[];
    float4* xs = smem;

    const int b0 = blockIdx.x * NB;

    // --- Stage x tile: 4 rows x 4096 floats = 64 KB ---
    for (int i = threadIdx.x; i < NCHUNK; i += THREADS) {
        const float* xb = x + (size_t)b0 * NCHUNK + i;
        float t0 = xb[0 * NCHUNK];
        float t1 = xb[1 * NCHUNK];
        float t2 = xb[2 * NCHUNK];
        float t3 = xb[3 * NCHUNK];
        xs[i] = make_float4(t0, t1, t2, t3);
    }
    __syncthreads();

    // --- Gather + dot: thread = class (2 per thread), 4 batch rows each ---
    for (int c = threadIdx.x; c < NCLASS; c += THREADS) {
        float a0 = 0.f, a1 = 0.f, a2 = 0.f, a3 = 0.f;
#pragma unroll 2
        for (int k = 0; k < NSUPP / 8; ++k) {       // 8 entries per chunk
            int4   pi = g_idx[k * NCLASS + c];      // 8 u16 idx, LDG.128
            float4 wa = g_w[(2 * k) * NCLASS + c];  // slots 8k..8k+3
            float4 wb = g_w[(2 * k + 1) * NCLASS + c];

            int i0 = pi.x & 0xffff, i1 = ((unsigned)pi.x) >> 16;
            int i2 = pi.y & 0xffff, i3 = ((unsigned)pi.y) >> 16;
            int i4 = pi.z & 0xffff, i5 = ((unsigned)pi.z) >> 16;
            int i6 = pi.w & 0xffff, i7 = ((unsigned)pi.w) >> 16;

            float4 v;
            v = xs[i0]; a0 = fmaf(v.x, wa.x, a0); a1 = fmaf(v.y, wa.x, a1);
                        a2 = fmaf(v.z, wa.x, a2); a3 = fmaf(v.w, wa.x, a3);
            v = xs[i1]; a0 = fmaf(v.x, wa.y, a0); a1 = fmaf(v.y, wa.y, a1);
                        a2 = fmaf(v.z, wa.y, a2); a3 = fmaf(v.w, wa.y, a3);
            v = xs[i2]; a0 = fmaf(v.x, wa.z, a0); a1 = fmaf(v.y, wa.z, a1);
                        a2 = fmaf(v.z, wa.z, a2); a3 = fmaf(v.w, wa.z, a3);
            v = xs[i3]; a0 = fmaf(v.x, wa.w, a0); a1 = fmaf(v.y, wa.w, a1);
                        a2 = fmaf(v.z, wa.w, a2); a3 = fmaf(v.w, wa.w, a3);
            v = xs[i4]; a0 = fmaf(v.x, wb.x, a0); a1 = fmaf(v.y, wb.x, a1);
                        a2 = fmaf(v.z, wb.x, a2); a3 = fmaf(v.w, wb.x, a3);
            v = xs[i5]; a0 = fmaf(v.x, wb.y, a0); a1 = fmaf(v.y, wb.y, a1);
                        a2 = fmaf(v.z, wb.y, a2); a3 = fmaf(v.w, wb.y, a3);
            v = xs[i6]; a0 = fmaf(v.x, wb.z, a0); a1 = fmaf(v.y, wb.z, a1);
                        a2 = fmaf(v.z, wb.z, a2); a3 = fmaf(v.w, wb.z, a3);
            v = xs[i7]; a0 = fmaf(v.x, wb.w, a0); a1 = fmaf(v.y, wb.w, a1);
                        a2 = fmaf(v.z, wb.w, a2); a3 = fmaf(v.w, wb.w, a3);
        }

        float* o = out + (size_t)b0 * NCLASS + c;
        o[0 * NCLASS] = __expf(a0);
        o[1 * NCLASS] = __expf(a1);
        o[2 * NCLASS] = __expf(a2);
        o[3 * NCLASS] = __expf(a3);
    }
}

extern "C" void kernel_launch(void* const* d_in, const int* in_sizes, int n_in,
                              void* d_out, int out_size) {
    const float* x    = (const float*)d_in[0];  // [4096, 4096] f32
    const float* w    = (const float*)d_in[1];  // [1000, 64]   f32
    const int*   cmap = (const int*)d_in[2];    // [1000, 64]   i32
    float*       out  = (float*)d_out;          // [4096, 1000] f32

    (void)in_sizes; (void)n_in; (void)out_size;

    static const size_t smem_bytes = NCHUNK * sizeof(float4);  // 64 KB
    cudaFuncSetAttribute(supp_kernel,
                         cudaFuncAttributeMaxDynamicSharedMemorySize,
                         (int)smem_bytes);

    pack_kernel<<<(NCLASS * 8 + 127) / 128, 128>>>(w, cmap);
    supp_kernel<<<BATCH / NB, THREADS, smem_bytes>>>(x, out);
}